// round 16
// baseline (speedup 1.0000x reference)
#include <cuda_runtime.h>
#include <cuda_bf16.h>
#include <cuda_fp16.h>
#include <math.h>
#include <mma.h>

using namespace nvcuda;

// ---------------------------------------------------------------------------
// SchNet interaction block (sm_100 base target — no tcgen05).
//  - edge filter: paired fp16 LUT (one 16B load = both lerp rows) + half2
//    lerp/mul arithmetic + fp16 x-gather + fp32 TMA reduce
//  - node GEMMs: tf32 wmma, 32-row CTA (validated); gemm1 emits x as fp16
//  - build_table + memset forked onto 2nd stream
// ---------------------------------------------------------------------------

#define HID   256
#define NG    50
#define TILE  32
#define SPAD  36
#define NTHREADS 256

#define CUTOFF_F 10.0f
#define LN2_F    0.69314718055994530942f
#define PI_F     3.14159265358979323846f

#define NT    2048
#define DMAX  17.3206f

#define MAXN 25000
__device__ __half g_xh[(size_t)MAXN * HID];        // fp16 x = h @ lin1_w
__device__ float  g_agg[(size_t)MAXN * HID];
// paired LUT: entry (t, c4) = 8 halves {T[t][4c..4c+3], T[t+1][4c..4c+3]}
__device__ __half g_table[(size_t)NT * HID * 2];
__device__ float  g_wtf[3][HID * HID];             // tf32 weights, [k][n]

__device__ __forceinline__ float ssp(float v) {
    return fmaxf(v, 0.0f) + log1pf(expf(-fabsf(v))) - LN2_F;
}

__device__ __forceinline__ float to_tf32(float x) {
    unsigned u;
    asm("cvt.rna.tf32.f32 %0, %1;" : "=r"(u) : "f"(x));
    return __uint_as_float(u);
}

// ---------------------------------------------------------------------------
__global__ void prep_weights(const float* __restrict__ w0,
                             const float* __restrict__ w1,
                             const float* __restrict__ w2)
{
    int which = blockIdx.y;
    const float* w = (which == 0) ? w0 : (which == 1) ? w1 : w2;
    int k = blockIdx.x;
    int n = threadIdx.x;
    g_wtf[which][k * HID + n] = to_tf32(w[k * HID + n]);
}

// ---------------------------------------------------------------------------
// tf32 wmma node GEMM (validated tiling). out_h != nullptr -> fp16 output.
// ---------------------------------------------------------------------------
#define NROWS 32
#define GLD 264
#define NODE_SMEM (NROWS * GLD * 4)      // 33792 B

__global__ __launch_bounds__(NTHREADS) void node_wmma(
    const float* __restrict__ A,
    const float* __restrict__ W1, const float* __restrict__ b1, int act1,
    const float* __restrict__ W2, const float* __restrict__ b2,
    float* __restrict__ out, __half* __restrict__ out_h, int nnodes)
{
    extern __shared__ float buf[];       // [NROWS][GLD]
    const int tid = threadIdx.x;
    const int wid = tid >> 5;
    const int n0 = blockIdx.x * NROWS;
    const int c0 = wid * 32;

    for (int i = tid; i < NROWS * 64; i += NTHREADS) {
        int row = i >> 6, c4 = (i & 63) << 2;
        float4 v = make_float4(0.f, 0.f, 0.f, 0.f);
        if (n0 + row < nnodes)
            v = *(const float4*)(A + (size_t)(n0 + row) * HID + c4);
        buf[row * GLD + c4 + 0] = to_tf32(v.x);
        buf[row * GLD + c4 + 1] = to_tf32(v.y);
        buf[row * GLD + c4 + 2] = to_tf32(v.z);
        buf[row * GLD + c4 + 3] = to_tf32(v.w);
    }
    __syncthreads();

    wmma::fragment<wmma::accumulator, 16, 16, 8, float> acc[2][2];

    #pragma unroll
    for (int m = 0; m < 2; m++)
        #pragma unroll
        for (int j = 0; j < 2; j++)
            wmma::fill_fragment(acc[m][j], 0.0f);

    #pragma unroll 2
    for (int kk = 0; kk < HID / 8; kk++) {
        wmma::fragment<wmma::matrix_a, 16, 16, 8, wmma::precision::tf32, wmma::row_major> af[2];
        #pragma unroll
        for (int m = 0; m < 2; m++)
            wmma::load_matrix_sync(af[m], buf + (m * 16) * GLD + kk * 8, GLD);
        wmma::fragment<wmma::matrix_b, 16, 16, 8, wmma::precision::tf32, wmma::row_major> bf;
        #pragma unroll
        for (int j = 0; j < 2; j++) {
            wmma::load_matrix_sync(bf, W1 + (size_t)kk * 8 * HID + c0 + j * 16, HID);
            #pragma unroll
            for (int m = 0; m < 2; m++)
                wmma::mma_sync(acc[m][j], af[m], bf, acc[m][j]);
        }
    }
    __syncthreads();
    #pragma unroll
    for (int m = 0; m < 2; m++)
        #pragma unroll
        for (int j = 0; j < 2; j++)
            wmma::store_matrix_sync(buf + (m * 16) * GLD + c0 + j * 16,
                                    acc[m][j], GLD, wmma::mem_row_major);
    __syncthreads();

    if (W2 == nullptr) {
        float bb = b1 ? b1[tid] : 0.0f;
        #pragma unroll 4
        for (int r = 0; r < NROWS; r++) {
            if (n0 + r < nnodes) {
                float v = buf[r * GLD + tid] + bb;
                if (act1) v = ssp(v);
                if (out_h)
                    out_h[(size_t)(n0 + r) * HID + tid] = __float2half_rn(v);
                else
                    out[(size_t)(n0 + r) * HID + tid] = v;
            }
        }
        return;
    }

    {
        float bb = b1 ? b1[tid] : 0.0f;
        #pragma unroll 4
        for (int r = 0; r < NROWS; r++) {
            float v = buf[r * GLD + tid] + bb;
            if (act1) v = ssp(v);
            buf[r * GLD + tid] = to_tf32(v);
        }
    }
    __syncthreads();

    #pragma unroll
    for (int m = 0; m < 2; m++)
        #pragma unroll
        for (int j = 0; j < 2; j++)
            wmma::fill_fragment(acc[m][j], 0.0f);

    #pragma unroll 2
    for (int kk = 0; kk < HID / 8; kk++) {
        wmma::fragment<wmma::matrix_a, 16, 16, 8, wmma::precision::tf32, wmma::row_major> af[2];
        #pragma unroll
        for (int m = 0; m < 2; m++)
            wmma::load_matrix_sync(af[m], buf + (m * 16) * GLD + kk * 8, GLD);
        wmma::fragment<wmma::matrix_b, 16, 16, 8, wmma::precision::tf32, wmma::row_major> bf;
        #pragma unroll
        for (int j = 0; j < 2; j++) {
            wmma::load_matrix_sync(bf, W2 + (size_t)kk * 8 * HID + c0 + j * 16, HID);
            #pragma unroll
            for (int m = 0; m < 2; m++)
                wmma::mma_sync(acc[m][j], af[m], bf, acc[m][j]);
        }
    }
    __syncthreads();
    #pragma unroll
    for (int m = 0; m < 2; m++)
        #pragma unroll
        for (int j = 0; j < 2; j++)
            wmma::store_matrix_sync(buf + (m * 16) * GLD + c0 + j * 16,
                                    acc[m][j], GLD, wmma::mem_row_major);
    __syncthreads();

    {
        float bb = b2 ? b2[tid] : 0.0f;
        #pragma unroll 4
        for (int r = 0; r < NROWS; r++) {
            if (n0 + r < nnodes)
                out[(size_t)(n0 + r) * HID + tid] = buf[r * GLD + tid] + bb;
        }
    }
}

// ---------------------------------------------------------------------------
// Build LUT (fp32 SIMT compute, fp16 paired store).
// Entry layout (halves): table[(t*64 + c4)*8 + 0..3] = row t  cols 4c..4c+3
//                        table[(t*64 + c4)*8 + 4..7] = row t+1 cols 4c..4c+3
// Row t's value is written to entry t (a-half) and entry t-1 (b-half).
// ---------------------------------------------------------------------------
__global__ __launch_bounds__(NTHREADS) void build_table(
    const float* __restrict__ w1, const float* __restrict__ b1,
    const float* __restrict__ w2, const float* __restrict__ b2,
    __half* __restrict__ table)
{
    __shared__ __align__(16) float eaT[NG * SPAD];
    __shared__ __align__(16) float t1T[HID * SPAD];
    __shared__ float C_s[TILE];

    const int tid = threadIdx.x;
    const int t0  = blockIdx.x * TILE;
    const float dx = DMAX / (float)(NT - 1);

    if (tid < TILE) {
        float d = (float)(t0 + tid) * dx;
        C_s[tid] = 0.5f * (cosf(d * (PI_F / CUTOFF_F)) + 1.0f);
    }

    const float step  = CUTOFF_F / (float)(NG - 1);
    const float coeff = -0.5f / (step * step);
    for (int idx = tid; idx < TILE * NG; idx += NTHREADS) {
        int e = idx / NG, g = idx % NG;
        float d = (float)(t0 + e) * dx;
        float diff = d - (float)g * step;
        eaT[g * SPAD + e] = expf(coeff * diff * diff);
    }
    __syncthreads();

    const int f = tid;
    float acc[TILE];
    {
        float bv = b1[f];
        #pragma unroll
        for (int e = 0; e < TILE; e++) acc[e] = bv;
        #pragma unroll 2
        for (int g = 0; g < NG; g++) {
            float wv = w1[g * HID + f];
            const float4* p = (const float4*)&eaT[g * SPAD];
            #pragma unroll
            for (int q = 0; q < TILE / 4; q++) {
                float4 v = p[q];
                acc[4*q+0] = fmaf(v.x, wv, acc[4*q+0]);
                acc[4*q+1] = fmaf(v.y, wv, acc[4*q+1]);
                acc[4*q+2] = fmaf(v.z, wv, acc[4*q+2]);
                acc[4*q+3] = fmaf(v.w, wv, acc[4*q+3]);
            }
        }
        #pragma unroll
        for (int e = 0; e < TILE; e++) t1T[f * SPAD + e] = ssp(acc[e]);
    }
    __syncthreads();
    {
        float bv = b2[f];
        #pragma unroll
        for (int e = 0; e < TILE; e++) acc[e] = bv;
        #pragma unroll 4
        for (int j = 0; j < HID; j++) {
            float wv = w2[j * HID + f];
            const float4* p = (const float4*)&t1T[j * SPAD];
            #pragma unroll
            for (int q = 0; q < TILE / 4; q++) {
                float4 v = p[q];
                acc[4*q+0] = fmaf(v.x, wv, acc[4*q+0]);
                acc[4*q+1] = fmaf(v.y, wv, acc[4*q+1]);
                acc[4*q+2] = fmaf(v.z, wv, acc[4*q+2]);
                acc[4*q+3] = fmaf(v.w, wv, acc[4*q+3]);
            }
        }
        const int c4 = f >> 2, w4 = f & 3;
        #pragma unroll
        for (int e = 0; e < TILE; e++) {
            int t = t0 + e;
            __half hv = __float2half_rn(acc[e] * C_s[e]);
            table[((size_t)t * 64 + c4) * 8 + w4] = hv;            // a-half of t
            if (t > 0)
                table[((size_t)(t - 1) * 64 + c4) * 8 + 4 + w4] = hv;  // b-half of t-1
        }
    }
}

// ---------------------------------------------------------------------------
// Edge kernel: one uint4 paired-table load + uint2 fp16 x load per iter;
// lerp + multiply fully in half2; fp32 msg -> TMA bulk-reduce.
// ---------------------------------------------------------------------------
#define EB 32
#define EDGE_SMEM_BYTES (EB * HID * 4)   // 32 KB

__global__ __launch_bounds__(NTHREADS, 4) void edge_lut_kernel(
    const __half* __restrict__ xh, const float* __restrict__ pos,
    const int* __restrict__ edge_index,
    const __half* __restrict__ table,
    float* __restrict__ agg, int nedges)
{
    extern __shared__ float msg[];       // [EB][HID]
    __shared__ int   row_s[EB];
    __shared__ int   col_s[EB];
    __shared__ int   idx_s[EB];
    __shared__ float u_s[EB];

    const int tid   = threadIdx.x;
    const int grp   = tid >> 6;
    const int lane4 = tid & 63;
    const int e0    = blockIdx.x * EB;
    const float inv_dx = (float)(NT - 1) / DMAX;

    if (tid < EB) {
        int e = e0 + tid;
        int r = 0, c = 0, ti = 0;
        float u = 0.0f;
        if (e < nedges) {
            r = edge_index[e];
            c = edge_index[nedges + e];
            float dxp = pos[3*r+0] - pos[3*c+0];
            float dyp = pos[3*r+1] - pos[3*c+1];
            float dzp = pos[3*r+2] - pos[3*c+2];
            float d = sqrtf(dxp*dxp + dyp*dyp + dzp*dzp);
            float s = d * inv_dx;
            ti = (int)s;
            if (ti > NT - 2) ti = NT - 2;
            u = s - (float)ti;
        }
        row_s[tid] = r; col_s[tid] = c; idx_s[tid] = ti; u_s[tid] = u;
    }
    __syncthreads();

    const uint4* tabp = (const uint4*)table;   // [NT][64] x 16B paired
    const uint2* xh4  = (const uint2*)xh;      // [N][64]  x 8B (4 halves)

    uint4 t0v;
    uint2 v0;
    {
        int i = grp;
        t0v = tabp[(size_t)idx_s[i] * 64 + lane4];
        v0  = xh4[(size_t)row_s[i] * 64 + lane4];
    }
    #pragma unroll
    for (int it = 0; it < EB / 4; it++) {
        uint4 t1v;
        uint2 v1;
        if (it < EB / 4 - 1) {
            int i = grp + (it + 1) * 4;
            t1v = tabp[(size_t)idx_s[i] * 64 + lane4];
            v1  = xh4[(size_t)row_s[i] * 64 + lane4];
        }
        int i = grp + it * 4;
        __half2 u2 = __float2half2_rn(u_s[i]);
        __half2 a01 = *(const __half2*)&t0v.x;
        __half2 a23 = *(const __half2*)&t0v.y;
        __half2 b01 = *(const __half2*)&t0v.z;
        __half2 b23 = *(const __half2*)&t0v.w;
        __half2 w01 = __hfma2(__hsub2(b01, a01), u2, a01);
        __half2 w23 = __hfma2(__hsub2(b23, a23), u2, a23);
        __half2 m01 = __hmul2(*(const __half2*)&v0.x, w01);
        __half2 m23 = __hmul2(*(const __half2*)&v0.y, w23);
        float2 f01 = __half22float2(m01);
        float2 f23 = __half22float2(m23);
        float4 m = make_float4(f01.x, f01.y, f23.x, f23.y);
        ((float4*)(msg + i * HID))[lane4] = m;
        t0v = t1v; v0 = v1;
    }
    __syncthreads();
    asm volatile("fence.proxy.async.shared::cta;" ::: "memory");

    if (tid < EB && (e0 + tid) < nedges) {
        unsigned saddr = (unsigned)__cvta_generic_to_shared(msg + tid * HID);
        float* gdst = agg + (size_t)col_s[tid] * HID;
        asm volatile(
            "cp.reduce.async.bulk.global.shared::cta.bulk_group.add.f32 [%0], [%1], %2;"
            :: "l"(gdst), "r"(saddr), "r"(HID * 4) : "memory");
        asm volatile("cp.async.bulk.commit_group;" ::: "memory");
        asm volatile("cp.async.bulk.wait_group 0;" ::: "memory");
    }
}

// ---------------------------------------------------------------------------
extern "C" void kernel_launch(void* const* d_in, const int* in_sizes, int n_in,
                              void* d_out, int out_size)
{
    const float* h      = (const float*)d_in[0];
    const float* pos    = (const float*)d_in[1];
    const float* lin1_w = (const float*)d_in[2];
    const float* lin2_w = (const float*)d_in[3];
    const float* lin2_b = (const float*)d_in[4];
    const float* mlp_w1 = (const float*)d_in[5];
    const float* mlp_b1 = (const float*)d_in[6];
    const float* mlp_w2 = (const float*)d_in[7];
    const float* mlp_b2 = (const float*)d_in[8];
    const float* lin_w  = (const float*)d_in[9];
    const float* lin_b  = (const float*)d_in[10];
    const int*   eidx   = (const int*)d_in[11];

    const int nnodes = in_sizes[0] / HID;
    const int nedges = in_sizes[11] / 2;

    float *aggb = nullptr, *wtf = nullptr;
    __half *tabl = nullptr, *xh = nullptr;
    cudaGetSymbolAddress((void**)&xh, g_xh);
    cudaGetSymbolAddress((void**)&aggb, g_agg);
    cudaGetSymbolAddress((void**)&tabl, g_table);
    cudaGetSymbolAddress((void**)&wtf, g_wtf);

    float* out_f = (float*)d_out;

    static cudaStream_t s2 = nullptr;
    static cudaEvent_t evFork = nullptr, evJoin = nullptr;
    if (!s2) {
        cudaFuncSetAttribute(edge_lut_kernel,
                             cudaFuncAttributeMaxDynamicSharedMemorySize,
                             EDGE_SMEM_BYTES);
        cudaFuncSetAttribute(node_wmma,
                             cudaFuncAttributeMaxDynamicSharedMemorySize,
                             NODE_SMEM);
        cudaStreamCreateWithFlags(&s2, cudaStreamNonBlocking);
        cudaEventCreateWithFlags(&evFork, cudaEventDisableTiming);
        cudaEventCreateWithFlags(&evJoin, cudaEventDisableTiming);
    }

    const int nblk_wmma  = (nnodes + NROWS - 1) / NROWS;
    const int nblk_edges = (nedges + EB - 1) / EB;

    // fork: build_table + agg memset on s2, concurrent with prep+gemm1 on main
    cudaEventRecord(evFork, 0);
    cudaStreamWaitEvent(s2, evFork, 0);
    cudaMemsetAsync(aggb, 0, (size_t)nnodes * HID * sizeof(float), s2);
    build_table<<<NT / TILE, NTHREADS, 0, s2>>>(mlp_w1, mlp_b1, mlp_w2, mlp_b2, tabl);
    cudaEventRecord(evJoin, s2);

    prep_weights<<<dim3(HID, 3), HID>>>(lin1_w, lin2_w, lin_w);
    // x = h @ lin1_w, emitted as fp16
    node_wmma<<<nblk_wmma, NTHREADS, NODE_SMEM>>>(
        h, wtf + 0 * HID * HID, nullptr, 0, nullptr, nullptr,
        nullptr, xh, nnodes);

    cudaStreamWaitEvent(0, evJoin, 0);   // join before edge kernel

    edge_lut_kernel<<<nblk_edges, NTHREADS, EDGE_SMEM_BYTES>>>(
        xh, pos, eidx, tabl, aggb, nedges);

    // out = ssp(agg @ lin2_w + b) @ lin_w + b  (fused, fp32 out)
    node_wmma<<<nblk_wmma, NTHREADS, NODE_SMEM>>>(
        aggb, wtf + 1 * HID * HID, lin2_b, 1,
        wtf + 2 * HID * HID, lin_b, out_f, nullptr, nnodes);

    if (out_size >= nnodes * HID + nnodes * 3) {
        cudaMemcpyAsync(out_f + (size_t)nnodes * HID, pos,
                        (size_t)nnodes * 3 * sizeof(float),
                        cudaMemcpyDeviceToDevice);
    }
}

// round 17
// speedup vs baseline: 1.1024x; 1.1024x over previous
#include <cuda_runtime.h>
#include <cuda_bf16.h>
#include <cuda_fp16.h>
#include <math.h>
#include <mma.h>

using namespace nvcuda;

// ---------------------------------------------------------------------------
// SchNet interaction block (sm_100 base target — no tcgen05).
//  - edge filter: paired fp16 LUT + half2 lerp + fp16 x + fp32 TMA reduce
//    (round-16 validated, 103.5us, at L2 cap — frozen)
//  - node GEMMs: fp16 wmma m16n16k16 (same 11-bit mantissa as tf32, half the
//    weight L2 traffic — node GEMMs are weight-bandwidth-bound) (new)
//  - build_table + memset forked onto 2nd stream
// ---------------------------------------------------------------------------

#define HID   256
#define NG    50
#define TILE  32
#define SPAD  36
#define NTHREADS 256

#define CUTOFF_F 10.0f
#define LN2_F    0.69314718055994530942f
#define PI_F     3.14159265358979323846f

#define NT    2048
#define DMAX  17.3206f

#define MAXN 25000
__device__ __half g_xh[(size_t)MAXN * HID];        // fp16 x = h @ lin1_w
__device__ float  g_agg[(size_t)MAXN * HID];
// paired LUT: entry (t, c4) = 8 halves {T[t][4c..4c+3], T[t+1][4c..4c+3]}
__device__ __half g_table[(size_t)NT * HID * 2];
__device__ __half g_wh[3][HID * HID];              // fp16 weights, [k][n]

__device__ __forceinline__ float ssp(float v) {
    return fmaxf(v, 0.0f) + log1pf(expf(-fabsf(v))) - LN2_F;
}

// ---------------------------------------------------------------------------
__global__ void prep_weights(const float* __restrict__ w0,
                             const float* __restrict__ w1,
                             const float* __restrict__ w2)
{
    int which = blockIdx.y;
    const float* w = (which == 0) ? w0 : (which == 1) ? w1 : w2;
    int k = blockIdx.x;
    int n = threadIdx.x;
    g_wh[which][k * HID + n] = __float2half_rn(w[k * HID + n]);
}

// ---------------------------------------------------------------------------
// fp16 wmma node GEMM (m16n16k16, fp32 accum), optionally fused 2-stage:
//   Y = act1( A @ W1 + b1 );  out = (W2 ? Y @ W2 + b2 : Y)
// 32 rows/CTA, 8 warps x 32-col strips (acc 2x2). A tile in half smem.
// ---------------------------------------------------------------------------
#define NROWS 32
#define GLD_H 272                          // half elements per A-tile row
#define GLD   264                          // float elements per stage row
#define AH_BYTES   (NROWS * GLD_H * 2)     // 17408
#define NODE_SMEM  (AH_BYTES + NROWS * GLD * 4)   // 17408 + 33792 = 51200

__global__ __launch_bounds__(NTHREADS) void node_wmma(
    const float* __restrict__ A,
    const __half* __restrict__ W1, const float* __restrict__ b1, int act1,
    const __half* __restrict__ W2, const float* __restrict__ b2,
    float* __restrict__ out, __half* __restrict__ out_h, int nnodes)
{
    extern __shared__ char smraw[];
    __half* ah   = (__half*)smraw;                 // [NROWS][GLD_H]
    float* stage = (float*)(smraw + AH_BYTES);     // [NROWS][GLD]

    const int tid = threadIdx.x;
    const int wid = tid >> 5;
    const int n0 = blockIdx.x * NROWS;
    const int c0 = wid * 32;

    // ---- stage A rows as fp16 ----
    for (int i = tid; i < NROWS * 64; i += NTHREADS) {
        int row = i >> 6, c4 = (i & 63) << 2;
        float4 v = make_float4(0.f, 0.f, 0.f, 0.f);
        if (n0 + row < nnodes)
            v = *(const float4*)(A + (size_t)(n0 + row) * HID + c4);
        __half* p = ah + row * GLD_H + c4;
        p[0] = __float2half_rn(v.x);
        p[1] = __float2half_rn(v.y);
        p[2] = __float2half_rn(v.z);
        p[3] = __float2half_rn(v.w);
    }
    __syncthreads();

    wmma::fragment<wmma::accumulator, 16, 16, 16, float> acc[2][2];

    // ---- stage 1: A @ W1 ----
    #pragma unroll
    for (int m = 0; m < 2; m++)
        #pragma unroll
        for (int j = 0; j < 2; j++)
            wmma::fill_fragment(acc[m][j], 0.0f);

    #pragma unroll 2
    for (int kk = 0; kk < HID / 16; kk++) {
        wmma::fragment<wmma::matrix_a, 16, 16, 16, __half, wmma::row_major> af[2];
        #pragma unroll
        for (int m = 0; m < 2; m++)
            wmma::load_matrix_sync(af[m], ah + (m * 16) * GLD_H + kk * 16, GLD_H);
        wmma::fragment<wmma::matrix_b, 16, 16, 16, __half, wmma::row_major> bf;
        #pragma unroll
        for (int j = 0; j < 2; j++) {
            wmma::load_matrix_sync(bf, W1 + (size_t)kk * 16 * HID + c0 + j * 16, HID);
            #pragma unroll
            for (int m = 0; m < 2; m++)
                wmma::mma_sync(acc[m][j], af[m], bf, acc[m][j]);
        }
    }
    #pragma unroll
    for (int m = 0; m < 2; m++)
        #pragma unroll
        for (int j = 0; j < 2; j++)
            wmma::store_matrix_sync(stage + (m * 16) * GLD + c0 + j * 16,
                                    acc[m][j], GLD, wmma::mem_row_major);
    __syncthreads();

    if (W2 == nullptr) {
        float bb = b1 ? b1[tid] : 0.0f;
        #pragma unroll 4
        for (int r = 0; r < NROWS; r++) {
            if (n0 + r < nnodes) {
                float v = stage[r * GLD + tid] + bb;
                if (act1) v = ssp(v);
                if (out_h)
                    out_h[(size_t)(n0 + r) * HID + tid] = __float2half_rn(v);
                else
                    out[(size_t)(n0 + r) * HID + tid] = v;
            }
        }
        return;
    }

    // ---- elementwise: Y = half( act1(stage + b1) ) back into A tile ----
    {
        float bb = b1 ? b1[tid] : 0.0f;
        #pragma unroll 4
        for (int r = 0; r < NROWS; r++) {
            float v = stage[r * GLD + tid] + bb;
            if (act1) v = ssp(v);
            ah[r * GLD_H + tid] = __float2half_rn(v);
        }
    }
    __syncthreads();

    // ---- stage 2: Y @ W2 ----
    #pragma unroll
    for (int m = 0; m < 2; m++)
        #pragma unroll
        for (int j = 0; j < 2; j++)
            wmma::fill_fragment(acc[m][j], 0.0f);

    #pragma unroll 2
    for (int kk = 0; kk < HID / 16; kk++) {
        wmma::fragment<wmma::matrix_a, 16, 16, 16, __half, wmma::row_major> af[2];
        #pragma unroll
        for (int m = 0; m < 2; m++)
            wmma::load_matrix_sync(af[m], ah + (m * 16) * GLD_H + kk * 16, GLD_H);
        wmma::fragment<wmma::matrix_b, 16, 16, 16, __half, wmma::row_major> bf;
        #pragma unroll
        for (int j = 0; j < 2; j++) {
            wmma::load_matrix_sync(bf, W2 + (size_t)kk * 16 * HID + c0 + j * 16, HID);
            #pragma unroll
            for (int m = 0; m < 2; m++)
                wmma::mma_sync(acc[m][j], af[m], bf, acc[m][j]);
        }
    }
    __syncthreads();   // stage buffer reads from elementwise pass are done
    #pragma unroll
    for (int m = 0; m < 2; m++)
        #pragma unroll
        for (int j = 0; j < 2; j++)
            wmma::store_matrix_sync(stage + (m * 16) * GLD + c0 + j * 16,
                                    acc[m][j], GLD, wmma::mem_row_major);
    __syncthreads();

    {
        float bb = b2 ? b2[tid] : 0.0f;
        #pragma unroll 4
        for (int r = 0; r < NROWS; r++) {
            if (n0 + r < nnodes)
                out[(size_t)(n0 + r) * HID + tid] = stage[r * GLD + tid] + bb;
        }
    }
}

// ---------------------------------------------------------------------------
// Build LUT (fp32 SIMT compute, fp16 paired store) — round-16 validated.
// ---------------------------------------------------------------------------
__global__ __launch_bounds__(NTHREADS) void build_table(
    const float* __restrict__ w1, const float* __restrict__ b1,
    const float* __restrict__ w2, const float* __restrict__ b2,
    __half* __restrict__ table)
{
    __shared__ __align__(16) float eaT[NG * SPAD];
    __shared__ __align__(16) float t1T[HID * SPAD];
    __shared__ float C_s[TILE];

    const int tid = threadIdx.x;
    const int t0  = blockIdx.x * TILE;
    const float dx = DMAX / (float)(NT - 1);

    if (tid < TILE) {
        float d = (float)(t0 + tid) * dx;
        C_s[tid] = 0.5f * (cosf(d * (PI_F / CUTOFF_F)) + 1.0f);
    }

    const float step  = CUTOFF_F / (float)(NG - 1);
    const float coeff = -0.5f / (step * step);
    for (int idx = tid; idx < TILE * NG; idx += NTHREADS) {
        int e = idx / NG, g = idx % NG;
        float d = (float)(t0 + e) * dx;
        float diff = d - (float)g * step;
        eaT[g * SPAD + e] = expf(coeff * diff * diff);
    }
    __syncthreads();

    const int f = tid;
    float acc[TILE];
    {
        float bv = b1[f];
        #pragma unroll
        for (int e = 0; e < TILE; e++) acc[e] = bv;
        #pragma unroll 2
        for (int g = 0; g < NG; g++) {
            float wv = w1[g * HID + f];
            const float4* p = (const float4*)&eaT[g * SPAD];
            #pragma unroll
            for (int q = 0; q < TILE / 4; q++) {
                float4 v = p[q];
                acc[4*q+0] = fmaf(v.x, wv, acc[4*q+0]);
                acc[4*q+1] = fmaf(v.y, wv, acc[4*q+1]);
                acc[4*q+2] = fmaf(v.z, wv, acc[4*q+2]);
                acc[4*q+3] = fmaf(v.w, wv, acc[4*q+3]);
            }
        }
        #pragma unroll
        for (int e = 0; e < TILE; e++) t1T[f * SPAD + e] = ssp(acc[e]);
    }
    __syncthreads();
    {
        float bv = b2[f];
        #pragma unroll
        for (int e = 0; e < TILE; e++) acc[e] = bv;
        #pragma unroll 4
        for (int j = 0; j < HID; j++) {
            float wv = w2[j * HID + f];
            const float4* p = (const float4*)&t1T[j * SPAD];
            #pragma unroll
            for (int q = 0; q < TILE / 4; q++) {
                float4 v = p[q];
                acc[4*q+0] = fmaf(v.x, wv, acc[4*q+0]);
                acc[4*q+1] = fmaf(v.y, wv, acc[4*q+1]);
                acc[4*q+2] = fmaf(v.z, wv, acc[4*q+2]);
                acc[4*q+3] = fmaf(v.w, wv, acc[4*q+3]);
            }
        }
        const int c4 = f >> 2, w4 = f & 3;
        #pragma unroll
        for (int e = 0; e < TILE; e++) {
            int t = t0 + e;
            __half hv = __float2half_rn(acc[e] * C_s[e]);
            table[((size_t)t * 64 + c4) * 8 + w4] = hv;
            if (t > 0)
                table[((size_t)(t - 1) * 64 + c4) * 8 + 4 + w4] = hv;
        }
    }
}

// ---------------------------------------------------------------------------
// Edge kernel (round-16 validated, byte-identical): paired table + half2.
// ---------------------------------------------------------------------------
#define EB 32
#define EDGE_SMEM_BYTES (EB * HID * 4)   // 32 KB

__global__ __launch_bounds__(NTHREADS, 4) void edge_lut_kernel(
    const __half* __restrict__ xh, const float* __restrict__ pos,
    const int* __restrict__ edge_index,
    const __half* __restrict__ table,
    float* __restrict__ agg, int nedges)
{
    extern __shared__ float msg[];       // [EB][HID]
    __shared__ int   row_s[EB];
    __shared__ int   col_s[EB];
    __shared__ int   idx_s[EB];
    __shared__ float u_s[EB];

    const int tid   = threadIdx.x;
    const int grp   = tid >> 6;
    const int lane4 = tid & 63;
    const int e0    = blockIdx.x * EB;
    const float inv_dx = (float)(NT - 1) / DMAX;

    if (tid < EB) {
        int e = e0 + tid;
        int r = 0, c = 0, ti = 0;
        float u = 0.0f;
        if (e < nedges) {
            r = edge_index[e];
            c = edge_index[nedges + e];
            float dxp = pos[3*r+0] - pos[3*c+0];
            float dyp = pos[3*r+1] - pos[3*c+1];
            float dzp = pos[3*r+2] - pos[3*c+2];
            float d = sqrtf(dxp*dxp + dyp*dyp + dzp*dzp);
            float s = d * inv_dx;
            ti = (int)s;
            if (ti > NT - 2) ti = NT - 2;
            u = s - (float)ti;
        }
        row_s[tid] = r; col_s[tid] = c; idx_s[tid] = ti; u_s[tid] = u;
    }
    __syncthreads();

    const uint4* tabp = (const uint4*)table;   // [NT][64] x 16B paired
    const uint2* xh4  = (const uint2*)xh;      // [N][64]  x 8B (4 halves)

    uint4 t0v;
    uint2 v0;
    {
        int i = grp;
        t0v = tabp[(size_t)idx_s[i] * 64 + lane4];
        v0  = xh4[(size_t)row_s[i] * 64 + lane4];
    }
    #pragma unroll
    for (int it = 0; it < EB / 4; it++) {
        uint4 t1v;
        uint2 v1;
        if (it < EB / 4 - 1) {
            int i = grp + (it + 1) * 4;
            t1v = tabp[(size_t)idx_s[i] * 64 + lane4];
            v1  = xh4[(size_t)row_s[i] * 64 + lane4];
        }
        int i = grp + it * 4;
        __half2 u2 = __float2half2_rn(u_s[i]);
        __half2 a01 = *(const __half2*)&t0v.x;
        __half2 a23 = *(const __half2*)&t0v.y;
        __half2 b01 = *(const __half2*)&t0v.z;
        __half2 b23 = *(const __half2*)&t0v.w;
        __half2 w01 = __hfma2(__hsub2(b01, a01), u2, a01);
        __half2 w23 = __hfma2(__hsub2(b23, a23), u2, a23);
        __half2 m01 = __hmul2(*(const __half2*)&v0.x, w01);
        __half2 m23 = __hmul2(*(const __half2*)&v0.y, w23);
        float2 f01 = __half22float2(m01);
        float2 f23 = __half22float2(m23);
        float4 m = make_float4(f01.x, f01.y, f23.x, f23.y);
        ((float4*)(msg + i * HID))[lane4] = m;
        t0v = t1v; v0 = v1;
    }
    __syncthreads();
    asm volatile("fence.proxy.async.shared::cta;" ::: "memory");

    if (tid < EB && (e0 + tid) < nedges) {
        unsigned saddr = (unsigned)__cvta_generic_to_shared(msg + tid * HID);
        float* gdst = agg + (size_t)col_s[tid] * HID;
        asm volatile(
            "cp.reduce.async.bulk.global.shared::cta.bulk_group.add.f32 [%0], [%1], %2;"
            :: "l"(gdst), "r"(saddr), "r"(HID * 4) : "memory");
        asm volatile("cp.async.bulk.commit_group;" ::: "memory");
        asm volatile("cp.async.bulk.wait_group 0;" ::: "memory");
    }
}

// ---------------------------------------------------------------------------
extern "C" void kernel_launch(void* const* d_in, const int* in_sizes, int n_in,
                              void* d_out, int out_size)
{
    const float* h      = (const float*)d_in[0];
    const float* pos    = (const float*)d_in[1];
    const float* lin1_w = (const float*)d_in[2];
    const float* lin2_w = (const float*)d_in[3];
    const float* lin2_b = (const float*)d_in[4];
    const float* mlp_w1 = (const float*)d_in[5];
    const float* mlp_b1 = (const float*)d_in[6];
    const float* mlp_w2 = (const float*)d_in[7];
    const float* mlp_b2 = (const float*)d_in[8];
    const float* lin_w  = (const float*)d_in[9];
    const float* lin_b  = (const float*)d_in[10];
    const int*   eidx   = (const int*)d_in[11];

    const int nnodes = in_sizes[0] / HID;
    const int nedges = in_sizes[11] / 2;

    float *aggb = nullptr;
    __half *tabl = nullptr, *xh = nullptr, *wh = nullptr;
    cudaGetSymbolAddress((void**)&xh, g_xh);
    cudaGetSymbolAddress((void**)&aggb, g_agg);
    cudaGetSymbolAddress((void**)&tabl, g_table);
    cudaGetSymbolAddress((void**)&wh, g_wh);

    float* out_f = (float*)d_out;

    static cudaStream_t s2 = nullptr;
    static cudaEvent_t evFork = nullptr, evJoin = nullptr;
    if (!s2) {
        cudaFuncSetAttribute(edge_lut_kernel,
                             cudaFuncAttributeMaxDynamicSharedMemorySize,
                             EDGE_SMEM_BYTES);
        cudaFuncSetAttribute(node_wmma,
                             cudaFuncAttributeMaxDynamicSharedMemorySize,
                             NODE_SMEM);
        cudaStreamCreateWithFlags(&s2, cudaStreamNonBlocking);
        cudaEventCreateWithFlags(&evFork, cudaEventDisableTiming);
        cudaEventCreateWithFlags(&evJoin, cudaEventDisableTiming);
    }

    const int nblk_wmma  = (nnodes + NROWS - 1) / NROWS;
    const int nblk_edges = (nedges + EB - 1) / EB;

    // fork: build_table + agg memset on s2, concurrent with prep+gemm1 on main
    cudaEventRecord(evFork, 0);
    cudaStreamWaitEvent(s2, evFork, 0);
    cudaMemsetAsync(aggb, 0, (size_t)nnodes * HID * sizeof(float), s2);
    build_table<<<NT / TILE, NTHREADS, 0, s2>>>(mlp_w1, mlp_b1, mlp_w2, mlp_b2, tabl);
    cudaEventRecord(evJoin, s2);

    prep_weights<<<dim3(HID, 3), HID>>>(lin1_w, lin2_w, lin_w);
    // x = h @ lin1_w, emitted as fp16
    node_wmma<<<nblk_wmma, NTHREADS, NODE_SMEM>>>(
        h, wh + 0 * HID * HID, nullptr, 0, nullptr, nullptr,
        nullptr, xh, nnodes);

    cudaStreamWaitEvent(0, evJoin, 0);   // join before edge kernel

    edge_lut_kernel<<<nblk_edges, NTHREADS, EDGE_SMEM_BYTES>>>(
        xh, pos, eidx, tabl, aggb, nedges);

    // out = ssp(agg @ lin2_w + b) @ lin_w + b  (fused, fp32 out)
    node_wmma<<<nblk_wmma, NTHREADS, NODE_SMEM>>>(
        aggb, wh + 1 * HID * HID, lin2_b, 1,
        wh + 2 * HID * HID, lin_b, out_f, nullptr, nnodes);

    if (out_size >= nnodes * HID + nnodes * 3) {
        cudaMemcpyAsync(out_f + (size_t)nnodes * HID, pos,
                        (size_t)nnodes * 3 * sizeof(float),
                        cudaMemcpyDeviceToDevice);
    }
}